// round 11
// baseline (speedup 1.0000x reference)
#include <cuda_runtime.h>
#include <cuda_bf16.h>

// Contrastive loss v9: cp.async smem pipeline (bytes-in-flight without regs).
//   per pair p: sq = ||emb[a]-emb[b]||^2 ; d = sqrt(max(sq,1e-12))
//   loss_p = (1-i)*max(0,1-d)^2 + i*d^2 ; out = sum / (P+1e-10)
//
// Each warp owns a private 3-stage smem ring (4KB/stage = rows a+b). Copies
// for pairs i+1,i+2 are in flight (LDGSTS, no dest registers) while pair i is
// computed from smem. Lanes copy and read back their OWN 16B chunks -> no
// syncwarp, commit/wait_group only. 4 warps/block, 48KB dyn smem, 4 blocks/SM.

#define D_DIM      512
#define ROW_BYTES  (D_DIM * 4)            // 2048
#define STAGE_BYTES (2 * ROW_BYTES)       // 4096 (row a + row b)
#define STAGES     3
#define WARPS_PER_BLOCK 4
#define THREADS_PER_BLOCK (WARPS_PER_BLOCK * 32)
#define SMEM_BYTES (WARPS_PER_BLOCK * STAGES * STAGE_BYTES)   // 49152
#define MAX_BLOCKS 16384

__device__ float        g_partials[MAX_BLOCKS];
__device__ unsigned int g_counter = 0;

__device__ __forceinline__ unsigned int atom_add_acqrel(unsigned int* p,
                                                        unsigned int v) {
    unsigned int old;
    asm volatile("atom.acq_rel.gpu.global.add.u32 %0, [%1], %2;"
                 : "=r"(old) : "l"(p), "r"(v) : "memory");
    return old;
}

__device__ __forceinline__ void cp16(unsigned int smem_dst, const void* gsrc) {
    asm volatile("cp.async.cg.shared.global [%0], [%1], 16;"
                 :: "r"(smem_dst), "l"(gsrc));
}
__device__ __forceinline__ void cp_commit() {
    asm volatile("cp.async.commit_group;");
}
template <int N>
__device__ __forceinline__ void cp_wait() {
    asm volatile("cp.async.wait_group %0;" :: "n"(N));
}

// Issue the 8 x 16B per-lane copies for one pair into a stage.
// Layout per stage: row a at [0,2048), row b at [2048,4096);
// chunk k of a row: base + k*512 + lane*16 (gmem layout mirrored -> matched).
__device__ __forceinline__ void issue_pair(unsigned int stage_base,
                                           const char* __restrict__ embc,
                                           int ia, int ib, int lane)
{
    const char* ga = embc + (size_t)ia * ROW_BYTES + lane * 16;
    const char* gb = embc + (size_t)ib * ROW_BYTES + lane * 16;
    unsigned int sa = stage_base + lane * 16;
    #pragma unroll
    for (int k = 0; k < 4; ++k) {
        cp16(sa + k * 512,            ga + k * 512);
        cp16(sa + k * 512 + ROW_BYTES, gb + k * 512);
    }
}

__global__ __launch_bounds__(THREADS_PER_BLOCK)
void contrastive_pipe_kernel(const float* __restrict__ emb,
                             const int* __restrict__ pair_a,
                             const int* __restrict__ pair_b,
                             const int* __restrict__ pair_same,
                             float* __restrict__ out,
                             int P)
{
    extern __shared__ char smem[];
    const int warp_id     = threadIdx.x >> 5;
    const int lane        = threadIdx.x & 31;
    const int warp_global = blockIdx.x * WARPS_PER_BLOCK + warp_id;
    const int W           = gridDim.x * WARPS_PER_BLOCK;   // total warps

    const char* __restrict__ embc = reinterpret_cast<const char*>(emb);

    // This warp's private ring base (32-bit shared address for cp.async/LDS).
    unsigned int ring_base;
    {
        char* pbase = smem + warp_id * (STAGES * STAGE_BYTES);
        ring_base = (unsigned int)__cvta_generic_to_shared(pbase);
    }

    float warp_loss = 0.0f;   // lane 0 canonical

    int p_issue = warp_global;
    int p_comp  = warp_global;

    // Prologue: fill STAGES stages (commit empty groups past the end to keep
    // the group count aligned).
    #pragma unroll
    for (int s = 0; s < STAGES; ++s) {
        if (p_issue < P) {
            int ia = __ldg(pair_a + p_issue);
            int ib = __ldg(pair_b + p_issue);
            issue_pair(ring_base + s * STAGE_BYTES, embc, ia, ib, lane);
        }
        cp_commit();
        p_issue += W;
    }

    int stage = 0;
    while (p_comp < P) {
        cp_wait<STAGES - 1>();   // oldest group (this stage) complete

        const unsigned int sb = ring_base + stage * STAGE_BYTES;

        // Read back this lane's own chunks: 8 x LDS.128, conflict-free.
        float s = 0.0f;
        #pragma unroll
        for (int k = 0; k < 4; ++k) {
            float4 va, vb;
            unsigned int addr_a = sb + k * 512 + lane * 16;
            asm volatile("ld.shared.v4.f32 {%0,%1,%2,%3}, [%4];"
                         : "=f"(va.x), "=f"(va.y), "=f"(va.z), "=f"(va.w)
                         : "r"(addr_a));
            asm volatile("ld.shared.v4.f32 {%0,%1,%2,%3}, [%4];"
                         : "=f"(vb.x), "=f"(vb.y), "=f"(vb.z), "=f"(vb.w)
                         : "r"(addr_a + ROW_BYTES));
            float dx = va.x - vb.x, dy = va.y - vb.y;
            float dz = va.z - vb.z, dw = va.w - vb.w;
            s += dx * dx + dy * dy + dz * dz + dw * dw;
        }

        // Refill this stage with the next pending pair (reads above already
        // executed; cp.async data can't land before its ~global latency).
        if (p_issue < P) {
            int ia = __ldg(pair_a + p_issue);
            int ib = __ldg(pair_b + p_issue);
            issue_pair(sb, embc, ia, ib, lane);
        }
        cp_commit();
        p_issue += W;

        // Warp tree reduction (5 shfl) + loss.
        #pragma unroll
        for (int off = 16; off > 0; off >>= 1)
            s += __shfl_xor_sync(0xFFFFFFFFu, s, off);

        if (lane == 0) {
            float d = sqrtf(fmaxf(s, 1e-12f));
            float i = (float)__ldg(pair_same + p_comp);
            float h = fmaxf(0.0f, 1.0f - d);
            warp_loss += (1.0f - i) * h * h + i * d * d;
        }

        p_comp += W;
        stage = (stage == STAGES - 1) ? 0 : stage + 1;
    }
    cp_wait<0>();   // drain before smem reuse below

    // Block reduction of per-warp losses.
    __shared__ float s_loss[WARPS_PER_BLOCK];
    __shared__ bool  s_is_last;
    if (lane == 0) s_loss[warp_id] = warp_loss;
    __syncthreads();

    if (threadIdx.x == 0) {
        float acc = 0.0f;
        #pragma unroll
        for (int w = 0; w < WARPS_PER_BLOCK; ++w) acc += s_loss[w];
        g_partials[blockIdx.x] = acc;
        unsigned int prev = atom_add_acqrel(&g_counter, 1u);
        s_is_last = (prev == gridDim.x - 1);
        if (s_is_last) atomicExch(&g_counter, 0u);
    }
    __syncthreads();

    // Last block: deterministic final reduction in fixed index order.
    if (s_is_last) {
        __shared__ float s_fin[THREADS_PER_BLOCK];
        float acc = 0.0f;
        for (int i = threadIdx.x; i < (int)gridDim.x; i += THREADS_PER_BLOCK)
            acc += g_partials[i];
        s_fin[threadIdx.x] = acc;
        __syncthreads();
        #pragma unroll
        for (int off = THREADS_PER_BLOCK / 2; off > 0; off >>= 1) {
            if (threadIdx.x < off) s_fin[threadIdx.x] += s_fin[threadIdx.x + off];
            __syncthreads();
        }
        if (threadIdx.x == 0)
            out[0] = s_fin[0] / ((float)P + 1e-10f);
    }
}

extern "C" void kernel_launch(void* const* d_in, const int* in_sizes, int n_in,
                              void* d_out, int out_size)
{
    const float* emb       = (const float*)d_in[0];
    const int*   pair_a    = (const int*)d_in[1];
    const int*   pair_b    = (const int*)d_in[2];
    const int*   pair_same = (const int*)d_in[3];
    float*       out       = (float*)d_out;

    const int P = in_sizes[1];  // element count of pair_a

    static_assert(SMEM_BYTES == 49152, "ring smem");
    cudaFuncSetAttribute(contrastive_pipe_kernel,
                         cudaFuncAttributeMaxDynamicSharedMemorySize,
                         SMEM_BYTES);

    // 4 blocks/SM x 148 SMs = 592 blocks, 2368 warps, ~13.8 pairs/warp.
    int num_blocks = 592;
    int max_useful = (P + WARPS_PER_BLOCK - 1) / WARPS_PER_BLOCK;
    if (num_blocks > max_useful) num_blocks = max_useful;
    if (num_blocks < 1) num_blocks = 1;
    if (num_blocks > MAX_BLOCKS) num_blocks = MAX_BLOCKS;

    contrastive_pipe_kernel<<<num_blocks, THREADS_PER_BLOCK, SMEM_BYTES>>>(
        emb, pair_a, pair_b, pair_same, out, P);
}

// round 12
// speedup vs baseline: 1.3974x; 1.3974x over previous
#include <cuda_runtime.h>
#include <cuda_bf16.h>

// Contrastive loss v10 = v3 (best, 16.4us) with a BALANCED full-occupancy
// grid: 1184 blocks = 148 SMs x 8 resident blocks (regs=32 -> RF allows
// 2048 thr/SM exactly). v3's 1024 blocks left SMs at 6-7/8 blocks (occ 84%).
//
//   per pair p: sq = ||emb[a]-emb[b]||^2 ; d = sqrt(max(sq,1e-12))
//   loss_p = (1-i)*max(0,1-d)^2 + i*d^2 ; out = sum / (P+1e-10)

#define D_DIM 512
#define VEC_PER_ROW (D_DIM / 4)      // 128 float4 per row
#define WARPS_PER_BLOCK 8
#define THREADS_PER_BLOCK (WARPS_PER_BLOCK * 32)
#define BLOCKS_FULL (148 * 8)        // 1184: exactly 8 blocks per SM
#define MAX_BLOCKS 16384

__device__ float        g_partials[MAX_BLOCKS];
__device__ unsigned int g_counter = 0;

__device__ __forceinline__ unsigned int atom_add_acqrel(unsigned int* p,
                                                        unsigned int v) {
    unsigned int old;
    asm volatile("atom.acq_rel.gpu.global.add.u32 %0, [%1], %2;"
                 : "=r"(old) : "l"(p), "r"(v) : "memory");
    return old;
}

__global__ __launch_bounds__(THREADS_PER_BLOCK)
void contrastive_fused_kernel(const float* __restrict__ emb,
                              const int* __restrict__ pair_a,
                              const int* __restrict__ pair_b,
                              const int* __restrict__ pair_same,
                              float* __restrict__ out,
                              int P)
{
    const int warp_id     = threadIdx.x >> 5;
    const int lane        = threadIdx.x & 31;
    const int warp_global = blockIdx.x * WARPS_PER_BLOCK + warp_id;
    const int warp_stride = gridDim.x * WARPS_PER_BLOCK;

    const float4* __restrict__ embv = reinterpret_cast<const float4*>(emb);

    float warp_loss = 0.0f;   // meaningful on lane 0 only

    int p  = warp_global;
    int ia = 0, ib = 0;
    if (p < P) { ia = __ldg(pair_a + p); ib = __ldg(pair_b + p); }

    while (p < P) {
        // Prefetch next pair's indices (hides idx->row dependent chain).
        const int p_next = p + warp_stride;
        int ia_next = 0, ib_next = 0;
        if (p_next < P) {
            ia_next = __ldg(pair_a + p_next);
            ib_next = __ldg(pair_b + p_next);
        }

        const float4* __restrict__ ra = embv + (size_t)ia * VEC_PER_ROW;
        const float4* __restrict__ rb = embv + (size_t)ib * VEC_PER_ROW;

        // 8 independent 16B L2-only loads (512B/warp each, fully coalesced).
        float4 va[4], vb[4];
        #pragma unroll
        for (int k = 0; k < 4; ++k) {
            va[k] = __ldcg(ra + lane + k * 32);
            vb[k] = __ldcg(rb + lane + k * 32);
        }

        // ||a-b||^2 per lane.
        float s = 0.0f;
        #pragma unroll
        for (int k = 0; k < 4; ++k) {
            float dx = va[k].x - vb[k].x;
            float dy = va[k].y - vb[k].y;
            float dz = va[k].z - vb[k].z;
            float dw = va[k].w - vb[k].w;
            s += dx * dx + dy * dy + dz * dz + dw * dw;
        }

        // Warp tree reduction (5 shfl).
        #pragma unroll
        for (int off = 16; off > 0; off >>= 1)
            s += __shfl_xor_sync(0xFFFFFFFFu, s, off);

        if (lane == 0) {
            float sq = fmaxf(s, 1e-12f);
            float d = sqrtf(sq);
            float i = (float)__ldg(pair_same + p);
            float h = fmaxf(0.0f, 1.0f - d);
            warp_loss += (1.0f - i) * h * h + i * d * d;
        }

        p  = p_next;
        ia = ia_next;
        ib = ib_next;
    }

    // Block reduction of per-warp losses.
    __shared__ float s_loss[WARPS_PER_BLOCK];
    __shared__ bool  s_is_last;
    if (lane == 0) s_loss[warp_id] = warp_loss;
    __syncthreads();

    if (threadIdx.x == 0) {
        float acc = 0.0f;
        #pragma unroll
        for (int w = 0; w < WARPS_PER_BLOCK; ++w) acc += s_loss[w];
        g_partials[blockIdx.x] = acc;
        unsigned int prev = atom_add_acqrel(&g_counter, 1u);  // release-orders store
        s_is_last = (prev == gridDim.x - 1);
        if (s_is_last) atomicExch(&g_counter, 0u);  // replay-safe self-reset
    }
    __syncthreads();

    // Last block: deterministic final reduction in fixed index order.
    if (s_is_last) {
        __shared__ float s_fin[THREADS_PER_BLOCK];
        float acc = 0.0f;
        for (int i = threadIdx.x; i < (int)gridDim.x; i += THREADS_PER_BLOCK)
            acc += g_partials[i];
        s_fin[threadIdx.x] = acc;
        __syncthreads();
        #pragma unroll
        for (int off = THREADS_PER_BLOCK / 2; off > 0; off >>= 1) {
            if (threadIdx.x < off) s_fin[threadIdx.x] += s_fin[threadIdx.x + off];
            __syncthreads();
        }
        if (threadIdx.x == 0)
            out[0] = s_fin[0] / ((float)P + 1e-10f);
    }
}

extern "C" void kernel_launch(void* const* d_in, const int* in_sizes, int n_in,
                              void* d_out, int out_size)
{
    const float* emb       = (const float*)d_in[0];
    const int*   pair_a    = (const int*)d_in[1];
    const int*   pair_b    = (const int*)d_in[2];
    const int*   pair_same = (const int*)d_in[3];
    float*       out       = (float*)d_out;

    const int P = in_sizes[1];  // element count of pair_a

    // Balanced full-occupancy single wave: 8 blocks on each of 148 SMs.
    int num_blocks = BLOCKS_FULL;
    int max_useful = (P + WARPS_PER_BLOCK - 1) / WARPS_PER_BLOCK;
    if (num_blocks > max_useful) num_blocks = max_useful;
    if (num_blocks < 1) num_blocks = 1;
    if (num_blocks > MAX_BLOCKS) num_blocks = MAX_BLOCKS;

    contrastive_fused_kernel<<<num_blocks, THREADS_PER_BLOCK>>>(
        emb, pair_a, pair_b, pair_same, out, P);
}